// round 6
// baseline (speedup 1.0000x reference)
#include <cuda_runtime.h>
#include <cuda_fp16.h>
#include <cstdint>

#define E_ 8
#define D_ 512
#define F_ 2048
#define N_ 4096

#define BM 128
#define BN 128
#define BK 16          // k halves per tile
#define KSPLIT 2

#define ASTRIDE 24     // halves per smem row (48B, conflict-free, 16B-aligned)
#define STAGE_H (128 * ASTRIDE)   // 3072 halves per stage

#define WSZ ((size_t)E_ * D_ * F_)
#define XSZ ((size_t)N_ * D_)

// ---------------- scratch (no allocations allowed) ----------------
__device__ int g_counts[E_];
__device__ int g_expert[N_];
__device__ int g_pos[N_];
__device__ int g_row2tok[N_];
__device__ int g_rowexpert[N_];
__device__ __align__(16) __half g_W1h[WSZ];            // W1 transposed: [e][f][d], fp16
__device__ __align__(16) __half g_W2h[WSZ];            // W2 transposed: [e][d][f], fp16
__device__ __align__(16) __half g_xh[XSZ];             // x fp16
__device__ __align__(16) __half g_H[(size_t)N_ * F_];  // hidden fp16
__device__ __align__(16) float  g_part[KSPLIT][(size_t)N_ * D_];

// ---------------- helpers ----------------
__device__ __forceinline__ int imin(int a, int b) { return a < b ? a : b; }

__device__ __forceinline__ void cp_async16(void* sm, const void* gm) {
    uint32_t s = (uint32_t)__cvta_generic_to_shared(sm);
    asm volatile("cp.async.cg.shared.global [%0], [%1], 16;" :: "r"(s), "l"(gm));
}
__device__ __forceinline__ void cp_commit() { asm volatile("cp.async.commit_group;"); }
__device__ __forceinline__ void cp_wait1()  { asm volatile("cp.async.wait_group 1;"); }

__device__ __forceinline__ void mma_f16(float c[4], const uint32_t a[4], const uint32_t b[2]) {
    asm volatile(
        "mma.sync.aligned.m16n8k16.row.col.f32.f16.f16.f32 "
        "{%0,%1,%2,%3}, {%4,%5,%6,%7}, {%8,%9}, {%0,%1,%2,%3};"
        : "+f"(c[0]), "+f"(c[1]), "+f"(c[2]), "+f"(c[3])
        : "r"(a[0]), "r"(a[1]), "r"(a[2]), "r"(a[3]), "r"(b[0]), "r"(b[1]));
}

__device__ __forceinline__ int expert_off(int e) {
    int s = 0;
#pragma unroll
    for (int i = 0; i < E_; i++) if (i < e) s += g_counts[i];
    return s;
}

// ---------------- transpose + fp16 convert: W[R][C] -> Wt[C][R] per expert ----
// NOTE: destination selected in DEVICE code — never pass __device__ globals
// as kernel args from host (host shadow address; silently writes host memory
// via ATS on GB300).
__global__ void transpose_fp16(const float* __restrict__ W, int R, int C, int which) {
    __half* __restrict__ Wt = which ? g_W2h : g_W1h;
    __shared__ float tile[32][33];
    const int e = blockIdx.z;
    W  += (size_t)e * R * C;
    Wt += (size_t)e * R * C;
    const int c0 = blockIdx.x * 32;
    const int r0 = blockIdx.y * 32;
    const int tx = threadIdx.x;       // 0..31
    const int ty = threadIdx.y;       // 0..7
#pragma unroll
    for (int i = ty; i < 32; i += 8)
        tile[i][tx] = W[(size_t)(r0 + i) * C + c0 + tx];
    __syncthreads();
#pragma unroll
    for (int i = ty; i < 32; i += 8)
        Wt[(size_t)(c0 + i) * R + r0 + tx] = __float2half_rn(tile[tx][i]);
}

// ---------------- x fp16 convert + count init ----------------
__global__ void convert_x(const float* __restrict__ x) {
    if (blockIdx.x == 0 && threadIdx.x < E_) g_counts[threadIdx.x] = 0;
    int i = blockIdx.x * blockDim.x + threadIdx.x;   // float4 index
    if (i >= (int)(XSZ / 4)) return;
    float4 v = reinterpret_cast<const float4*>(x)[i];
    __half2 h0 = __floats2half2_rn(v.x, v.y);
    __half2 h1 = __floats2half2_rn(v.z, v.w);
    uint2 o = make_uint2(*(uint32_t*)&h0, *(uint32_t*)&h1);
    reinterpret_cast<uint2*>(g_xh)[i] = o;
}

// ---------------- gate: one warp per token (fp32, exact routing) ----------------
__global__ void gate_kernel(const float* __restrict__ x,
                            const float* __restrict__ Wg,
                            const float* __restrict__ bg) {
    int warp = (blockIdx.x * blockDim.x + threadIdx.x) >> 5;
    int lane = threadIdx.x & 31;
    if (warp >= N_) return;
    const float* xr = x + (size_t)warp * D_;

    float acc[E_];
#pragma unroll
    for (int e = 0; e < E_; e++) acc[e] = 0.f;
    for (int d = lane; d < D_; d += 32) {
        float xv = xr[d];
        const float4* w = reinterpret_cast<const float4*>(Wg + (size_t)d * E_);
        float4 w0 = w[0], w1 = w[1];
        acc[0] += xv * w0.x; acc[1] += xv * w0.y;
        acc[2] += xv * w0.z; acc[3] += xv * w0.w;
        acc[4] += xv * w1.x; acc[5] += xv * w1.y;
        acc[6] += xv * w1.z; acc[7] += xv * w1.w;
    }
#pragma unroll
    for (int off = 16; off > 0; off >>= 1)
#pragma unroll
        for (int e = 0; e < E_; e++)
            acc[e] += __shfl_down_sync(0xFFFFFFFFu, acc[e], off);
    if (lane == 0) {
        float best = acc[0] + bg[0];
        int bi = 0;
#pragma unroll
        for (int e = 1; e < E_; e++) {
            float v = acc[e] + bg[e];
            if (v > best) { best = v; bi = e; }
        }
        int p = atomicAdd(&g_counts[bi], 1);
        g_expert[warp] = bi;
        g_pos[warp]    = p;
    }
}

// ---------------- assign compacted rows ----------------
__global__ void assign_kernel() {
    int t = blockIdx.x * blockDim.x + threadIdx.x;
    if (t >= N_) return;
    int e = g_expert[t];
    int r = expert_off(e) + g_pos[t];
    g_row2tok[r]   = t;
    g_rowexpert[r] = e;
}

// =====================================================================
// fp16 GEMM core: 128 thr, 4 warps (2x2), warp tile 64x64 = 4x8 m16n8k16.
// A smem [128][24] (row=m, k contig), B smem [128][24] (row=n, k contig).
// 3-stage cp.async ring, one __syncthreads per k-iter.
// =====================================================================
#define GEMM_CORE(NK, AKSTEP, BKSTEP)                                             \
    __shared__ __align__(16) __half smA[3][STAGE_H];                              \
    __shared__ __align__(16) __half smB[3][STAGE_H];                              \
    const int lane = tid & 31;                                                    \
    const int warp = tid >> 5;                                                    \
    const int wm   = warp >> 1;                                                   \
    const int wn   = warp & 1;                                                    \
    float acc[4][8][4];                                                           \
    _Pragma("unroll") for (int i = 0; i < 4; i++)                                 \
    _Pragma("unroll") for (int j = 0; j < 8; j++)                                 \
    _Pragma("unroll") for (int q = 0; q < 4; q++) acc[i][j][q] = 0.f;             \
    _Pragma("unroll")                                                             \
    for (int s = 0; s < 2; s++) {                                                 \
        cp_async16(&smA[s][tid * ASTRIDE + 0], ap + (size_t)s * (AKSTEP));        \
        cp_async16(&smA[s][tid * ASTRIDE + 8], ap + (size_t)s * (AKSTEP) + 8);    \
        cp_async16(&smB[s][tid * ASTRIDE + 0], bp + (size_t)s * (BKSTEP));        \
        cp_async16(&smB[s][tid * ASTRIDE + 8], bp + (size_t)s * (BKSTEP) + 8);    \
        cp_commit();                                                              \
    }                                                                             \
    for (int it = 0; it < (NK); ++it) {                                           \
        cp_wait1();                                                               \
        __syncthreads();                                                          \
        if (it + 2 < (NK)) {                                                      \
            const int s = (it + 2) % 3;                                           \
            cp_async16(&smA[s][tid * ASTRIDE + 0], ap + (size_t)(it + 2) * (AKSTEP));     \
            cp_async16(&smA[s][tid * ASTRIDE + 8], ap + (size_t)(it + 2) * (AKSTEP) + 8); \
            cp_async16(&smB[s][tid * ASTRIDE + 0], bp + (size_t)(it + 2) * (BKSTEP));     \
            cp_async16(&smB[s][tid * ASTRIDE + 8], bp + (size_t)(it + 2) * (BKSTEP) + 8); \
        }                                                                         \
        cp_commit();                                                              \
        const int cur = it % 3;                                                   \
        const int kq  = (lane & 3) * 2;                                           \
        uint32_t a[4][4], b[8][2];                                                \
        _Pragma("unroll")                                                         \
        for (int mt = 0; mt < 4; ++mt) {                                          \
            const int r = wm * 64 + mt * 16 + (lane >> 2);                        \
            a[mt][0] = *(const uint32_t*)&smA[cur][r * ASTRIDE + kq];             \
            a[mt][1] = *(const uint32_t*)&smA[cur][(r + 8) * ASTRIDE + kq];       \
            a[mt][2] = *(const uint32_t*)&smA[cur][r * ASTRIDE + kq + 8];         \
            a[mt][3] = *(const uint32_t*)&smA[cur][(r + 8) * ASTRIDE + kq + 8];   \
        }                                                                         \
        _Pragma("unroll")                                                         \
        for (int nt = 0; nt < 8; ++nt) {                                          \
            const int c = wn * 64 + nt * 8 + (lane >> 2);                         \
            b[nt][0] = *(const uint32_t*)&smB[cur][c * ASTRIDE + kq];             \
            b[nt][1] = *(const uint32_t*)&smB[cur][c * ASTRIDE + kq + 8];         \
        }                                                                         \
        _Pragma("unroll")                                                         \
        for (int mt = 0; mt < 4; ++mt)                                            \
        _Pragma("unroll")                                                         \
        for (int nt = 0; nt < 8; ++nt)                                            \
            mma_f16(acc[mt][nt], a[mt], b[nt]);                                   \
    }

// ---------------- GEMM1: H = fp16(relu(x @ W1 + b1)) ----------------
__global__ __launch_bounds__(128, 2)
void gemm1_tc(const float* __restrict__ b1) {
    const int e   = blockIdx.z;
    const int cnt = g_counts[e];
    const int m0  = blockIdx.y * BM;
    if (m0 >= cnt) return;
    const int off = expert_off(e);
    const int n0  = blockIdx.x * BN;
    const int tid = threadIdx.x;

    const int arr = imin(m0 + tid, cnt - 1);
    const __half* ap = g_xh + (size_t)g_row2tok[off + arr] * D_;
    const __half* bp = g_W1h + (size_t)e * D_ * F_ + (size_t)(n0 + tid) * D_;

    GEMM_CORE(D_ / BK, BK, BK)

    const float* b1e = b1 + (size_t)e * F_;
#pragma unroll
    for (int mt = 0; mt < 4; ++mt) {
        const int rb = m0 + wm * 64 + mt * 16 + (lane >> 2);
#pragma unroll
        for (int half = 0; half < 2; ++half) {
            const int r = rb + half * 8;
            if (r < cnt) {
                __half* Hrow = g_H + (size_t)(off + r) * F_;
#pragma unroll
                for (int nt = 0; nt < 8; ++nt) {
                    const int c = n0 + wn * 64 + nt * 8 + (lane & 3) * 2;
                    float v0 = fmaxf(acc[mt][nt][half * 2 + 0] + b1e[c],     0.f);
                    float v1 = fmaxf(acc[mt][nt][half * 2 + 1] + b1e[c + 1], 0.f);
                    __half2 h = __floats2half2_rn(v0, v1);
                    *reinterpret_cast<__half2*>(Hrow + c) = h;
                }
            }
        }
    }
}

// ---------------- GEMM2 (split-K=2): g_part[kp] = H @ W2 ----------------
__global__ __launch_bounds__(128, 2)
void gemm2_tc() {
    const int e   = blockIdx.z;
    const int cnt = g_counts[e];
    const int m0  = blockIdx.y * BM;
    if (m0 >= cnt) return;
    const int off = expert_off(e);
    const int kp  = blockIdx.x >> 2;
    const int n0  = (blockIdx.x & 3) * BN;
    const int kbase = kp * (F_ / KSPLIT);
    const int tid = threadIdx.x;

    const int arr = imin(m0 + tid, cnt - 1);
    const __half* ap = g_H + (size_t)(off + arr) * F_ + kbase;
    const __half* bp = g_W2h + (size_t)e * D_ * F_ + (size_t)(n0 + tid) * F_ + kbase;

    GEMM_CORE((F_ / KSPLIT) / BK, BK, BK)

    float* part = g_part[kp];
#pragma unroll
    for (int mt = 0; mt < 4; ++mt) {
        const int rb = m0 + wm * 64 + mt * 16 + (lane >> 2);
#pragma unroll
        for (int half = 0; half < 2; ++half) {
            const int r = rb + half * 8;
            if (r < cnt) {
                float* prow = part + (size_t)(off + r) * D_;
#pragma unroll
                for (int nt = 0; nt < 8; ++nt) {
                    const int c = n0 + wn * 64 + nt * 8 + (lane & 3) * 2;
                    float2 o;
                    o.x = acc[mt][nt][half * 2 + 0];
                    o.y = acc[mt][nt][half * 2 + 1];
                    *reinterpret_cast<float2*>(prow + c) = o;
                }
            }
        }
    }
}

// ---------------- reduce: out[tok] = part0 + part1 + b2[e] ----------------
__global__ void reduce_kernel(const float* __restrict__ b2,
                              float* __restrict__ out) {
    int idx = blockIdx.x * blockDim.x + threadIdx.x;
    const int rowq = D_ / 4;
    if (idx >= N_ * rowq) return;
    int r  = idx / rowq;
    int c4 = idx - r * rowq;
    int tok = g_row2tok[r];
    int e   = g_rowexpert[r];
    float4 p0 = reinterpret_cast<const float4*>(g_part[0])[(size_t)r * rowq + c4];
    float4 p1 = reinterpret_cast<const float4*>(g_part[1])[(size_t)r * rowq + c4];
    float4 bb = reinterpret_cast<const float4*>(b2 + (size_t)e * D_)[c4];
    float4 o;
    o.x = p0.x + p1.x + bb.x;
    o.y = p0.y + p1.y + bb.y;
    o.z = p0.z + p1.z + bb.z;
    o.w = p0.w + p1.w + bb.w;
    reinterpret_cast<float4*>(out)[(size_t)tok * rowq + c4] = o;
}

// ---------------- launch ----------------
extern "C" void kernel_launch(void* const* d_in, const int* in_sizes, int n_in,
                              void* d_out, int out_size) {
    const float* x  = (const float*)d_in[0];
    const float* Wg = (const float*)d_in[1];
    const float* bg = (const float*)d_in[2];
    const float* W1 = (const float*)d_in[3];
    const float* b1 = (const float*)d_in[4];
    const float* W2 = (const float*)d_in[5];
    const float* b2 = (const float*)d_in[6];
    float* out = (float*)d_out;

    dim3 tb(32, 8);
    dim3 tg1(F_ / 32, D_ / 32, E_);   // W1 [D][F] -> [F][D]
    dim3 tg2(D_ / 32, F_ / 32, E_);   // W2 [F][D] -> [D][F]
    transpose_fp16<<<tg1, tb>>>(W1, D_, F_, 0);
    transpose_fp16<<<tg2, tb>>>(W2, F_, D_, 1);

    convert_x<<<(XSZ / 4 + 255) / 256, 256>>>(x);
    gate_kernel<<<(N_ * 32) / 256, 256>>>(x, Wg, bg);
    assign_kernel<<<N_ / 256, 256>>>();

    dim3 g1(F_ / BN, N_ / BM, E_);              // (16, 32, 8)
    gemm1_tc<<<g1, 128>>>(b1);

    dim3 g2((D_ / BN) * KSPLIT, N_ / BM, E_);   // (8, 32, 8)
    gemm2_tc<<<g2, 128>>>();

    reduce_kernel<<<(N_ * D_ / 4) / 256, 256>>>(b2, out);
}

// round 8
// speedup vs baseline: 1.4228x; 1.4228x over previous
#include <cuda_runtime.h>
#include <cuda_fp16.h>
#include <cstdint>

#define E_ 8
#define D_ 512
#define F_ 2048
#define N_ 4096
#define KSPLIT 2

#define BK 16                      // k halves per stage
#define NSTG 3

#define A_ROWS 128
#define A_STRIDE 24                // halves (48B rows, LDSM conflict-free)
#define B_ROWS 16
#define B_STRIDE 136               // halves (272B rows, LDSM conflict-free)

#define WSZ ((size_t)E_ * D_ * F_)
#define XSZ ((size_t)N_ * D_)

// ---------------- scratch (no allocations allowed) ----------------
__device__ int g_counts[E_];
__device__ int g_expert[N_];
__device__ int g_pos[N_];
__device__ int g_row2tok[N_];
__device__ int g_rowexpert[N_];
__device__ __align__(16) __half g_W1h[WSZ];            // W1 natural [e][d][f], fp16
__device__ __align__(16) __half g_W2h[WSZ];            // W2 natural [e][f][d], fp16
__device__ __align__(16) __half g_xh[XSZ];             // x fp16
__device__ __align__(16) __half g_H[(size_t)N_ * F_];  // hidden fp16
__device__ __align__(16) float  g_part[KSPLIT][(size_t)N_ * D_];

// ---------------- helpers ----------------
__device__ __forceinline__ int imin(int a, int b) { return a < b ? a : b; }

__device__ __forceinline__ void cp_async16_s(uint32_t sm, const void* gm) {
    asm volatile("cp.async.cg.shared.global [%0], [%1], 16;" :: "r"(sm), "l"(gm));
}
__device__ __forceinline__ void cp_commit() { asm volatile("cp.async.commit_group;"); }
__device__ __forceinline__ void cp_wait1()  { asm volatile("cp.async.wait_group 1;"); }

__device__ __forceinline__ void ldsm_x4(uint32_t r[4], uint32_t addr) {
    asm volatile("ldmatrix.sync.aligned.m8n8.x4.shared.b16 {%0,%1,%2,%3}, [%4];"
                 : "=r"(r[0]), "=r"(r[1]), "=r"(r[2]), "=r"(r[3]) : "r"(addr));
}
__device__ __forceinline__ void ldsm_x4_t(uint32_t r[4], uint32_t addr) {
    asm volatile("ldmatrix.sync.aligned.m8n8.x4.trans.shared.b16 {%0,%1,%2,%3}, [%4];"
                 : "=r"(r[0]), "=r"(r[1]), "=r"(r[2]), "=r"(r[3]) : "r"(addr));
}

__device__ __forceinline__ void mma_f16(float c[4], const uint32_t a[4],
                                        uint32_t b0, uint32_t b1) {
    asm volatile(
        "mma.sync.aligned.m16n8k16.row.col.f32.f16.f16.f32 "
        "{%0,%1,%2,%3}, {%4,%5,%6,%7}, {%8,%9}, {%0,%1,%2,%3};"
        : "+f"(c[0]), "+f"(c[1]), "+f"(c[2]), "+f"(c[3])
        : "r"(a[0]), "r"(a[1]), "r"(a[2]), "r"(a[3]), "r"(b0), "r"(b1));
}

__device__ __forceinline__ int expert_off(int e) {
    int s = 0;
#pragma unroll
    for (int i = 0; i < E_; i++) if (i < e) s += g_counts[i];
    return s;
}

// ---------------- prep: streaming fp16 convert of W1, W2 + counts init ----------
// (device globals referenced directly in device code — never as host-side args)
__global__ void prep_kernel(const float* __restrict__ W1, const float* __restrict__ W2) {
    if (blockIdx.x == 0 && threadIdx.x < E_) g_counts[threadIdx.x] = 0;
    const size_t n1 = WSZ / 4;            // float4 count per weight tensor
    const size_t total = 2 * n1;
    size_t stride = (size_t)gridDim.x * blockDim.x;
    for (size_t i = (size_t)blockIdx.x * blockDim.x + threadIdx.x; i < total; i += stride) {
        const float4* src; __half* dst; size_t j;
        if (i < n1) { src = (const float4*)W1; dst = g_W1h; j = i; }
        else        { src = (const float4*)W2; dst = g_W2h; j = i - n1; }
        float4 v = src[j];
        __half2 h0 = __floats2half2_rn(v.x, v.y);
        __half2 h1 = __floats2half2_rn(v.z, v.w);
        reinterpret_cast<uint2*>(dst)[j] = make_uint2(*(uint32_t*)&h0, *(uint32_t*)&h1);
    }
}

// ---------------- gate + x fp16 convert (fused single pass over x) ----------------
__global__ void gate_cvt_kernel(const float* __restrict__ x,
                                const float* __restrict__ Wg,
                                const float* __restrict__ bg) {
    int tok  = (blockIdx.x * blockDim.x + threadIdx.x) >> 5;
    int lane = threadIdx.x & 31;
    if (tok >= N_) return;
    const float4* xr = reinterpret_cast<const float4*>(x) + (size_t)tok * (D_ / 4);
    uint2* xo = reinterpret_cast<uint2*>(g_xh) + (size_t)tok * (D_ / 4);

    float acc[E_];
#pragma unroll
    for (int e = 0; e < E_; e++) acc[e] = 0.f;

#pragma unroll
    for (int q = 0; q < 4; q++) {
        int d4 = lane + q * 32;
        float4 v = xr[d4];
        __half2 h0 = __floats2half2_rn(v.x, v.y);
        __half2 h1 = __floats2half2_rn(v.z, v.w);
        xo[d4] = make_uint2(*(uint32_t*)&h0, *(uint32_t*)&h1);
        float vv[4] = {v.x, v.y, v.z, v.w};
#pragma unroll
        for (int t = 0; t < 4; t++) {
            const float4* w = reinterpret_cast<const float4*>(Wg + (size_t)(d4 * 4 + t) * E_);
            float4 w0 = w[0], w1 = w[1];
            acc[0] += vv[t] * w0.x; acc[1] += vv[t] * w0.y;
            acc[2] += vv[t] * w0.z; acc[3] += vv[t] * w0.w;
            acc[4] += vv[t] * w1.x; acc[5] += vv[t] * w1.y;
            acc[6] += vv[t] * w1.z; acc[7] += vv[t] * w1.w;
        }
    }
#pragma unroll
    for (int off = 16; off > 0; off >>= 1)
#pragma unroll
        for (int e = 0; e < E_; e++)
            acc[e] += __shfl_down_sync(0xFFFFFFFFu, acc[e], off);
    if (lane == 0) {
        float best = acc[0] + bg[0];
        int bi = 0;
#pragma unroll
        for (int e = 1; e < E_; e++) {
            float v = acc[e] + bg[e];
            if (v > best) { best = v; bi = e; }
        }
        int p = atomicAdd(&g_counts[bi], 1);
        g_expert[tok] = bi;
        g_pos[tok]    = p;
    }
}

// ---------------- assign compacted rows ----------------
__global__ void assign_kernel() {
    int t = blockIdx.x * blockDim.x + threadIdx.x;
    if (t >= N_) return;
    int e = g_expert[t];
    int r = expert_off(e) + g_pos[t];
    g_row2tok[r]   = t;
    g_rowexpert[r] = e;
}

// =====================================================================
// fp16 GEMM core: 256 thr, 8 warps (2x4), warp tile 64x32 = 4x4 m16n8k16.
// A smem [128][24] halves (row=m, k contig); B smem [16][136] (row=k, n contig).
// Fragments via ldmatrix: A 4x LDSM.x4, B 2x LDSM.x4.trans per k16 iter.
// 3-stage cp.async ring, one __syncthreads per iter. CWIDTH = B gmem row width.
// =====================================================================
#define GEMM_CORE(NK, CWIDTH)                                                     \
    __shared__ __align__(16) __half smA[NSTG][A_ROWS * A_STRIDE];                 \
    __shared__ __align__(16) __half smB[NSTG][B_ROWS * B_STRIDE];                 \
    const int lane = tid & 31;                                                    \
    const int warp = tid >> 5;                                                    \
    const int wm   = warp >> 2;        /* 0..1 */                                 \
    const int wn   = warp & 3;         /* 0..3 */                                 \
    const uint32_t sA0 = (uint32_t)__cvta_generic_to_shared(&smA[0][0]);          \
    const uint32_t sB0 = (uint32_t)__cvta_generic_to_shared(&smB[0][0]);          \
    /* per-thread load slots */                                                   \
    const int la_row = tid >> 1;                                                  \
    const int la_kc  = (tid & 1) * 8;                                             \
    const int lb_k   = tid >> 4;                                                  \
    const int lb_nc  = (tid & 15) * 8;                                            \
    const uint32_t dstA = sA0 + (la_row * A_STRIDE + la_kc) * 2;                  \
    const uint32_t dstB = sB0 + (lb_k * B_STRIDE + lb_nc) * 2;                    \
    /* fragment smem addresses (constant per thread) */                           \
    uint32_t adA[4], adB[2];                                                      \
    _Pragma("unroll")                                                             \
    for (int mt = 0; mt < 4; mt++)                                                \
        adA[mt] = sA0 + (((wm * 64 + mt * 16 + (lane & 15)) * A_STRIDE            \
                          + (lane >> 4) * 8)) * 2;                                \
    _Pragma("unroll")                                                             \
    for (int pr = 0; pr < 2; pr++) {                                              \
        const int j = lane >> 3;                                                  \
        const int kr = (j & 1) * 8 + (lane & 7);                                  \
        const int ncl = wn * 32 + pr * 16 + (j >> 1) * 8;                         \
        adB[pr] = sB0 + (kr * B_STRIDE + ncl) * 2;                                \
    }                                                                             \
    float acc[4][4][4];                                                           \
    _Pragma("unroll") for (int i = 0; i < 4; i++)                                 \
    _Pragma("unroll") for (int j = 0; j < 4; j++)                                 \
    _Pragma("unroll") for (int q = 0; q < 4; q++) acc[i][j][q] = 0.f;             \
    _Pragma("unroll")                                                             \
    for (int s = 0; s < 2; s++) {                                                 \
        cp_async16_s(dstA + s * (A_ROWS * A_STRIDE * 2), ap + (size_t)s * BK);    \
        cp_async16_s(dstB + s * (B_ROWS * B_STRIDE * 2), bp + (size_t)s * BK * (CWIDTH)); \
        cp_commit();                                                              \
    }                                                                             \
    for (int it = 0; it < (NK); ++it) {                                           \
        cp_wait1();                                                               \
        __syncthreads();                                                          \
        if (it + 2 < (NK)) {                                                      \
            const int s = (it + 2) % NSTG;                                        \
            cp_async16_s(dstA + s * (A_ROWS * A_STRIDE * 2), ap + (size_t)(it + 2) * BK); \
            cp_async16_s(dstB + s * (B_ROWS * B_STRIDE * 2), bp + (size_t)(it + 2) * BK * (CWIDTH)); \
        }                                                                         \
        cp_commit();                                                              \
        const int cur = it % NSTG;                                                \
        const uint32_t oA = cur * (A_ROWS * A_STRIDE * 2);                        \
        const uint32_t oB = cur * (B_ROWS * B_STRIDE * 2);                        \
        uint32_t a[4][4], bb[2][4];                                               \
        _Pragma("unroll")                                                         \
        for (int mt = 0; mt < 4; mt++) ldsm_x4(a[mt], adA[mt] + oA);              \
        _Pragma("unroll")                                                         \
        for (int pr = 0; pr < 2; pr++) ldsm_x4_t(bb[pr], adB[pr] + oB);           \
        _Pragma("unroll")                                                         \
        for (int mt = 0; mt < 4; mt++)                                            \
        _Pragma("unroll")                                                         \
        for (int nt = 0; nt < 4; nt++)                                            \
            mma_f16(acc[mt][nt], a[mt], bb[nt >> 1][(nt & 1) * 2],                \
                    bb[nt >> 1][(nt & 1) * 2 + 1]);                               \
    }

// ---------------- GEMM1: H = fp16(relu(x @ W1 + b1)) ----------------
__global__ __launch_bounds__(256, 2)
void gemm1_tc(const float* __restrict__ b1) {
    const int e   = blockIdx.z;
    const int cnt = g_counts[e];
    const int m0  = blockIdx.y * 128;
    if (m0 >= cnt) return;
    const int off = expert_off(e);
    const int n0  = blockIdx.x * 128;
    const int tid = threadIdx.x;

    // A gather row (constant per thread), B = W1 natural [d][f]
    const int arow = imin(m0 + (tid >> 1), cnt - 1);
    const __half* ap = g_xh + (size_t)g_row2tok[off + arow] * D_ + (tid & 1) * 8;
    const __half* bp = g_W1h + (size_t)e * D_ * F_ + (size_t)(tid >> 4) * F_ + n0 + (tid & 15) * 8;

    GEMM_CORE(D_ / BK, F_)     // 32 iters

    const float* b1e = b1 + (size_t)e * F_;
#pragma unroll
    for (int mt = 0; mt < 4; ++mt) {
        const int rb = m0 + wm * 64 + mt * 16 + (lane >> 2);
#pragma unroll
        for (int half = 0; half < 2; ++half) {
            const int r = rb + half * 8;
            if (r < cnt) {
                __half* Hrow = g_H + (size_t)(off + r) * F_;
#pragma unroll
                for (int nt = 0; nt < 4; ++nt) {
                    const int c = n0 + wn * 32 + nt * 8 + (lane & 3) * 2;
                    float v0 = fmaxf(acc[mt][nt][half * 2 + 0] + b1e[c],     0.f);
                    float v1 = fmaxf(acc[mt][nt][half * 2 + 1] + b1e[c + 1], 0.f);
                    __half2 h = __floats2half2_rn(v0, v1);
                    *reinterpret_cast<__half2*>(Hrow + c) = h;
                }
            }
        }
    }
}

// ---------------- GEMM2 (split-K=2): g_part[kp] = H @ W2 ----------------
__global__ __launch_bounds__(256, 2)
void gemm2_tc() {
    const int e   = blockIdx.z;
    const int cnt = g_counts[e];
    const int m0  = blockIdx.y * 128;
    if (m0 >= cnt) return;
    const int off = expert_off(e);
    const int kp  = blockIdx.x >> 2;
    const int n0  = (blockIdx.x & 3) * 128;
    const int kbase = kp * (F_ / KSPLIT);
    const int tid = threadIdx.x;

    const int arow = imin(m0 + (tid >> 1), cnt - 1);
    const __half* ap = g_H + (size_t)(off + arow) * F_ + kbase + (tid & 1) * 8;
    const __half* bp = g_W2h + (size_t)e * D_ * F_ + (size_t)(kbase + (tid >> 4)) * D_ + n0 + (tid & 15) * 8;

    GEMM_CORE((F_ / KSPLIT) / BK, D_)    // 64 iters

    float* part = g_part[kp];
#pragma unroll
    for (int mt = 0; mt < 4; ++mt) {
        const int rb = m0 + wm * 64 + mt * 16 + (lane >> 2);
#pragma unroll
        for (int half = 0; half < 2; ++half) {
            const int r = rb + half * 8;
            if (r < cnt) {
                float* prow = part + (size_t)(off + r) * D_;
#pragma unroll
                for (int nt = 0; nt < 4; ++nt) {
                    const int c = n0 + wn * 32 + nt * 8 + (lane & 3) * 2;
                    float2 o;
                    o.x = acc[mt][nt][half * 2 + 0];
                    o.y = acc[mt][nt][half * 2 + 1];
                    *reinterpret_cast<float2*>(prow + c) = o;
                }
            }
        }
    }
}

// ---------------- reduce: out[tok] = part0 + part1 + b2[e] ----------------
__global__ void reduce_kernel(const float* __restrict__ b2,
                              float* __restrict__ out) {
    int idx = blockIdx.x * blockDim.x + threadIdx.x;
    const int rowq = D_ / 4;
    if (idx >= N_ * rowq) return;
    int r  = idx / rowq;
    int c4 = idx - r * rowq;
    int tok = g_row2tok[r];
    int e   = g_rowexpert[r];
    float4 p0 = reinterpret_cast<const float4*>(g_part[0])[(size_t)r * rowq + c4];
    float4 p1 = reinterpret_cast<const float4*>(g_part[1])[(size_t)r * rowq + c4];
    float4 bb = reinterpret_cast<const float4*>(b2 + (size_t)e * D_)[c4];
    float4 o;
    o.x = p0.x + p1.x + bb.x;
    o.y = p0.y + p1.y + bb.y;
    o.z = p0.z + p1.z + bb.z;
    o.w = p0.w + p1.w + bb.w;
    reinterpret_cast<float4*>(out)[(size_t)tok * rowq + c4] = o;
}

// ---------------- launch ----------------
extern "C" void kernel_launch(void* const* d_in, const int* in_sizes, int n_in,
                              void* d_out, int out_size) {
    const float* x  = (const float*)d_in[0];
    const float* Wg = (const float*)d_in[1];
    const float* bg = (const float*)d_in[2];
    const float* W1 = (const float*)d_in[3];
    const float* b1 = (const float*)d_in[4];
    const float* W2 = (const float*)d_in[5];
    const float* b2 = (const float*)d_in[6];
    float* out = (float*)d_out;

    prep_kernel<<<1184, 256>>>(W1, W2);
    gate_cvt_kernel<<<(N_ * 32) / 256, 256>>>(x, Wg, bg);
    assign_kernel<<<N_ / 256, 256>>>();

    dim3 g1(F_ / 128, N_ / 128, E_);            // (16, 32, 8)
    gemm1_tc<<<g1, 256>>>(b1);

    dim3 g2((D_ / 128) * KSPLIT, N_ / 128, E_); // (8, 32, 8)
    gemm2_tc<<<g2, 256>>>();

    reduce_kernel<<<(N_ * D_ / 4) / 256, 256>>>(b2, out);
}